// round 4
// baseline (speedup 1.0000x reference)
#include <cuda_runtime.h>
#include <math.h>
#include <float.h>

// MoE gate: logits = hidden @ gate^T ; softmax over 8 experts; top-2; renormalize.
// hidden: [T, 4096] f32 (T = 16384), gate: [8, 4096] f32.
// Output (flattened f32): [T*2] topk weights, then [T*2] expert indices (as float).
//
// Lane layout: expert = lane>>2, h-sub = lane&3. Each lane accumulates ONE
// expert for TPW tokens over a quarter of its warp's h-range. H is split in
// half across warp pairs (HSPLIT=2) to double total warp count for latency
// hiding. Partial logits combined in smem; 8 lanes finalize top-2 + softmax.

#define NEXP   8
#define HDIM   4096
#define HV     (HDIM / 4)        // float4 per row = 1024
#define TPW    4                 // tokens per warp
#define HSPLIT 2
#define HHALF  (HDIM / HSPLIT)   // 2048 floats per warp
#define HHV    (HHALF / 4)       // 512 float4 per warp
#define ITERS  (HHALF / 16)      // 128: 16 floats (4 float4 across 4 h-sub lanes) per iter
#define PAIRS  4                 // token groups per block (256 thr = 8 warps = 4 pairs x 2 halves)
#define TOK_PER_BLOCK (PAIRS * TPW)  // 16

__global__ __launch_bounds__(256) void moe_gate_kernel(
    const float4* __restrict__ hid,
    const float4* __restrict__ gate,
    float* __restrict__ out,
    int n_tokens)
{
    const int lane = threadIdx.x & 31;
    const int w    = threadIdx.x >> 5;   // 0..7
    const int pair = w >> 1;             // 0..3
    const int half = w & 1;              // h-half
    const int tok0 = (blockIdx.x * PAIRS + pair) * TPW;
    const int e    = lane >> 2;          // expert owned by this lane
    const int hs   = lane & 3;           // h-sub slice

    if (tok0 >= n_tokens) return;

    const float4* g = gate + e * HV + half * HHV + hs;
    const float4* x = hid + (size_t)tok0 * HV + half * HHV + hs;

    float acc[TPW];
    #pragma unroll
    for (int t = 0; t < TPW; t++) acc[t] = 0.0f;

    #pragma unroll 2
    for (int it = 0; it < ITERS; it++) {
        const int o = it * 4;
        const float4 gv = g[o];
        #pragma unroll
        for (int t = 0; t < TPW; t++) {
            const float4 xv = x[(size_t)t * HV + o];
            acc[t] += xv.x * gv.x;
            acc[t] += xv.y * gv.y;
            acc[t] += xv.z * gv.z;
            acc[t] += xv.w * gv.w;
        }
    }

    // reduce over the 4 h-sub lanes (lanes 4e..4e+3 form a group; xor 1,2 stay in-group)
    #pragma unroll
    for (int t = 0; t < TPW; t++) {
        acc[t] += __shfl_xor_sync(0xffffffffu, acc[t], 1);
        acc[t] += __shfl_xor_sync(0xffffffffu, acc[t], 2);
    }

    __shared__ float part[PAIRS][HSPLIT][TPW][NEXP];
    if (hs == 0) {
        #pragma unroll
        for (int t = 0; t < TPW; t++)
            part[pair][half][t][e] = acc[t];
    }
    __syncthreads();

    // finalize: half-0 warps, lanes 0..TPW-1, one token each
    if (half == 0 && lane < TPW) {
        const int token = tok0 + lane;

        float l[NEXP];
        #pragma unroll
        for (int q = 0; q < NEXP; q++)
            l[q] = part[pair][0][lane][q] + part[pair][1][lane][q];

        // top-1 (strict > keeps lowest index on ties, matching lax.top_k)
        float b0 = l[0]; int i0 = 0;
        #pragma unroll
        for (int q = 1; q < NEXP; q++)
            if (l[q] > b0) { b0 = l[q]; i0 = q; }

        // top-2
        float b1 = -FLT_MAX; int i1 = 0;
        #pragma unroll
        for (int q = 0; q < NEXP; q++)
            if (q != i0 && l[q] > b1) { b1 = l[q]; i1 = q; }

        // renormalized top-2 softmax: w0 = e^{l0} / (e^{l0} + e^{l1})
        const float w0 = 1.0f / (1.0f + expf(b1 - b0));
        const float w1 = 1.0f - w0;

        float* out_idx = out + (size_t)n_tokens * 2;
        out[token * 2 + 0] = w0;
        out[token * 2 + 1] = w1;
        out_idx[token * 2 + 0] = (float)i0;
        out_idx[token * 2 + 1] = (float)i1;
    }
}

extern "C" void kernel_launch(void* const* d_in, const int* in_sizes, int n_in,
                              void* d_out, int out_size)
{
    const float* hid  = (const float*)d_in[0];   // hidden_states
    const float* gate = (const float*)d_in[1];   // gate_weight
    float* out = (float*)d_out;

    const int n_tokens = in_sizes[0] / HDIM;     // 16384
    const int blocks   = (n_tokens + TOK_PER_BLOCK - 1) / TOK_PER_BLOCK;  // 1024

    moe_gate_kernel<<<blocks, 256>>>(
        (const float4*)hid, (const float4*)gate, out, n_tokens);
}

// round 5
// speedup vs baseline: 3.0480x; 3.0480x over previous
#include <cuda_runtime.h>
#include <math.h>
#include <float.h>

// MoE gate: logits = hidden @ gate^T ; softmax over 8 experts; top-2; renormalize.
// hidden: [T, 4096] f32 (T = 16384), gate: [8, 4096] f32.
// Output (flattened f32): [T*2] topk weights, then [T*2] expert indices (as float).
//
// Dataflow (R0-style, proven): each lane loads a DISTINCT float4 of x per token
// per iter (full 512B-coalesced warp loads), accumulates partials for all 8
// experts on its slice. H split in half across warp pairs to double warp count.
// e-outer inner loop keeps only one gate vector live -> ~60 regs -> 4 blocks/SM.

#define NEXP   8
#define HDIM   4096
#define HV     (HDIM / 4)        // float4 per row = 1024
#define TPW    4                 // tokens per warp
#define HSPLIT 2
#define HHV    (HV / HSPLIT)     // 512 float4 per warp's half
#define ITERS  (HHV / 32)        // 16 iters: 32 lanes x float4 = 128 floats/iter
#define PAIRS  4                 // token groups per block (8 warps = 4 pairs x 2 halves)
#define TOK_PER_BLOCK (PAIRS * TPW)  // 16

__global__ __launch_bounds__(256, 4) void moe_gate_kernel(
    const float4* __restrict__ hid,
    const float4* __restrict__ gate,
    float* __restrict__ out,
    int n_tokens)
{
    const int lane = threadIdx.x & 31;
    const int w    = threadIdx.x >> 5;   // 0..7
    const int pair = w >> 1;             // token group 0..3
    const int half = w & 1;              // h-half
    const int tok0 = (blockIdx.x * PAIRS + pair) * TPW;
    if (tok0 >= n_tokens) return;

    const float4* xb = hid  + (size_t)tok0 * HV + half * HHV;
    const float4* gb = gate + half * HHV;

    float acc[TPW][NEXP];
    #pragma unroll
    for (int t = 0; t < TPW; t++)
        #pragma unroll
        for (int e = 0; e < NEXP; e++)
            acc[t][e] = 0.0f;

    #pragma unroll 1
    for (int it = 0; it < ITERS; it++) {
        const int hv = it * 32 + lane;

        // 4 independent streaming loads, 512B coalesced each (front-batched MLP)
        const float4 x0 = __ldcs(&xb[0 * (size_t)HV + hv]);
        const float4 x1 = __ldcs(&xb[1 * (size_t)HV + hv]);
        const float4 x2 = __ldcs(&xb[2 * (size_t)HV + hv]);
        const float4 x3 = __ldcs(&xb[3 * (size_t)HV + hv]);

        #pragma unroll
        for (int e = 0; e < NEXP; e++) {
            const float4 g = __ldg(&gb[e * HV + hv]);   // L1-resident (128KB total)
            acc[0][e] += x0.x*g.x + x0.y*g.y + x0.z*g.z + x0.w*g.w;
            acc[1][e] += x1.x*g.x + x1.y*g.y + x1.z*g.z + x1.w*g.w;
            acc[2][e] += x2.x*g.x + x2.y*g.y + x2.z*g.z + x2.w*g.w;
            acc[3][e] += x3.x*g.x + x3.y*g.y + x3.z*g.z + x3.w*g.w;
        }
    }

    // butterfly reduce across the 32 lanes for every (t,e)
    #pragma unroll
    for (int t = 0; t < TPW; t++) {
        #pragma unroll
        for (int e = 0; e < NEXP; e++) {
            float v = acc[t][e];
            v += __shfl_xor_sync(0xffffffffu, v, 16);
            v += __shfl_xor_sync(0xffffffffu, v, 8);
            v += __shfl_xor_sync(0xffffffffu, v, 4);
            v += __shfl_xor_sync(0xffffffffu, v, 2);
            v += __shfl_xor_sync(0xffffffffu, v, 1);
            acc[t][e] = v;
        }
    }

    __shared__ float part[PAIRS][HSPLIT][TPW][NEXP];
    #pragma unroll
    for (int e = 0; e < NEXP; e++) {
        if (lane == e) {          // static indexing -> stays in registers
            #pragma unroll
            for (int t = 0; t < TPW; t++)
                part[pair][half][t][e] = acc[t][e];
        }
    }
    __syncthreads();

    // finalize: half-0 warps, lanes 0..TPW-1, one token each
    if (half == 0 && lane < TPW) {
        const int token = tok0 + lane;

        float l[NEXP];
        #pragma unroll
        for (int q = 0; q < NEXP; q++)
            l[q] = part[pair][0][lane][q] + part[pair][1][lane][q];

        // top-1 (strict > keeps lowest index on ties, matching lax.top_k)
        float b0 = l[0]; int i0 = 0;
        #pragma unroll
        for (int q = 1; q < NEXP; q++)
            if (l[q] > b0) { b0 = l[q]; i0 = q; }

        // top-2
        float b1 = -FLT_MAX; int i1 = 0;
        #pragma unroll
        for (int q = 0; q < NEXP; q++)
            if (q != i0 && l[q] > b1) { b1 = l[q]; i1 = q; }

        // renormalized top-2 softmax: w0 = e^{l0} / (e^{l0} + e^{l1})
        const float w0 = 1.0f / (1.0f + expf(b1 - b0));
        const float w1 = 1.0f - w0;

        float* out_idx = out + (size_t)n_tokens * 2;
        out[token * 2 + 0] = w0;
        out[token * 2 + 1] = w1;
        out_idx[token * 2 + 0] = (float)i0;
        out_idx[token * 2 + 1] = (float)i1;
    }
}

extern "C" void kernel_launch(void* const* d_in, const int* in_sizes, int n_in,
                              void* d_out, int out_size)
{
    const float* hid  = (const float*)d_in[0];   // hidden_states
    const float* gate = (const float*)d_in[1];   // gate_weight
    float* out = (float*)d_out;

    const int n_tokens = in_sizes[0] / HDIM;     // 16384
    const int blocks   = (n_tokens + TOK_PER_BLOCK - 1) / TOK_PER_BLOCK;  // 1024

    moe_gate_kernel<<<blocks, 256>>>(
        (const float4*)hid, (const float4*)gate, out, n_tokens);
}

// round 7
// speedup vs baseline: 3.1520x; 1.0341x over previous
#include <cuda_runtime.h>
#include <math.h>
#include <float.h>

// MoE gate: logits = hidden @ gate^T ; softmax over 8 experts; top-2; renormalize.
// hidden: [T, 4096] f32 (T = 16384), gate: [8, 4096] f32.
// Output (flattened f32): [T*2] topk weights, then [T*2] expert indices (as float).
//
// R4 dataflow (512B-coalesced x loads, all-expert partials per lane) plus a
// ping-pong software pipeline: next iteration's 4 x-loads are issued BEFORE the
// current iteration's 128-FFMA burst, keeping a full 2KB load batch in flight
// per warp throughout compute (R4 serialized load->compute within a warp,
// duty-cycling the memory system to ~46% of peak).

#define NEXP   8
#define HDIM   4096
#define HV     (HDIM / 4)        // float4 per row = 1024
#define TPW    4                 // tokens per warp
#define HSPLIT 2
#define HHV    (HV / HSPLIT)     // 512 float4 per warp's half
#define ITERS  (HHV / 32)        // 16 iters: 32 lanes x float4 = 128 floats/iter
#define PAIRS  4                 // token groups per block (8 warps = 4 pairs x 2 halves)
#define TOK_PER_BLOCK (PAIRS * TPW)  // 16

#define LOAD_X(buf, hv)                                          \
    do {                                                         \
        buf[0] = __ldcs(&xb[0 * (size_t)HV + (hv)]);             \
        buf[1] = __ldcs(&xb[1 * (size_t)HV + (hv)]);             \
        buf[2] = __ldcs(&xb[2 * (size_t)HV + (hv)]);             \
        buf[3] = __ldcs(&xb[3 * (size_t)HV + (hv)]);             \
    } while (0)

#define COMPUTE(buf, hv)                                                      \
    do {                                                                      \
        _Pragma("unroll")                                                     \
        for (int e = 0; e < NEXP; e++) {                                      \
            const float4 g = __ldg(&gb[e * HV + (hv)]);                       \
            acc[0][e] += buf[0].x*g.x + buf[0].y*g.y + buf[0].z*g.z + buf[0].w*g.w; \
            acc[1][e] += buf[1].x*g.x + buf[1].y*g.y + buf[1].z*g.z + buf[1].w*g.w; \
            acc[2][e] += buf[2].x*g.x + buf[2].y*g.y + buf[2].z*g.z + buf[2].w*g.w; \
            acc[3][e] += buf[3].x*g.x + buf[3].y*g.y + buf[3].z*g.z + buf[3].w*g.w; \
        }                                                                     \
    } while (0)

__global__ __launch_bounds__(256, 3) void moe_gate_kernel(
    const float4* __restrict__ hid,
    const float4* __restrict__ gate,
    float* __restrict__ out,
    int n_tokens)
{
    const int lane = threadIdx.x & 31;
    const int w    = threadIdx.x >> 5;   // 0..7
    const int pair = w >> 1;             // token group 0..3
    const int half = w & 1;              // h-half
    const int tok0 = (blockIdx.x * PAIRS + pair) * TPW;
    if (tok0 >= n_tokens) return;

    const float4* xb = hid  + (size_t)tok0 * HV + half * HHV;
    const float4* gb = gate + half * HHV;

    float acc[TPW][NEXP];
    #pragma unroll
    for (int t = 0; t < TPW; t++)
        #pragma unroll
        for (int e = 0; e < NEXP; e++)
            acc[t][e] = 0.0f;

    float4 xa[TPW], xc[TPW];

    // prologue: load iter 0 into A
    LOAD_X(xa, lane);

    // ping-pong: load next batch before computing current
    #pragma unroll 1
    for (int it = 0; it < ITERS - 2; it += 2) {
        const int hva = it * 32 + lane;
        LOAD_X(xc, hva + 32);            // prefetch it+1 into C
        COMPUTE(xa, hva);                // compute it
        LOAD_X(xa, hva + 64);            // prefetch it+2 into A
        COMPUTE(xc, hva + 32);           // compute it+1
    }
    {   // epilogue: iters ITERS-2, ITERS-1 (A holds ITERS-2)
        const int hva = (ITERS - 2) * 32 + lane;
        LOAD_X(xc, hva + 32);
        COMPUTE(xa, hva);
        COMPUTE(xc, hva + 32);
    }

    // butterfly reduce across the 32 lanes for every (t,e)
    #pragma unroll
    for (int t = 0; t < TPW; t++) {
        #pragma unroll
        for (int e = 0; e < NEXP; e++) {
            float v = acc[t][e];
            v += __shfl_xor_sync(0xffffffffu, v, 16);
            v += __shfl_xor_sync(0xffffffffu, v, 8);
            v += __shfl_xor_sync(0xffffffffu, v, 4);
            v += __shfl_xor_sync(0xffffffffu, v, 2);
            v += __shfl_xor_sync(0xffffffffu, v, 1);
            acc[t][e] = v;
        }
    }

    __shared__ float part[PAIRS][HSPLIT][TPW][NEXP];
    #pragma unroll
    for (int e = 0; e < NEXP; e++) {
        if (lane == e) {          // static indexing -> stays in registers
            #pragma unroll
            for (int t = 0; t < TPW; t++)
                part[pair][half][t][e] = acc[t][e];
        }
    }
    __syncthreads();

    // finalize: half-0 warps, lanes 0..TPW-1, one token each
    if (half == 0 && lane < TPW) {
        const int token = tok0 + lane;

        float l[NEXP];
        #pragma unroll
        for (int q = 0; q < NEXP; q++)
            l[q] = part[pair][0][lane][q] + part[pair][1][lane][q];

        // top-1 (strict > keeps lowest index on ties, matching lax.top_k)
        float b0 = l[0]; int i0 = 0;
        #pragma unroll
        for (int q = 1; q < NEXP; q++)
            if (l[q] > b0) { b0 = l[q]; i0 = q; }

        // top-2
        float b1 = -FLT_MAX; int i1 = 0;
        #pragma unroll
        for (int q = 0; q < NEXP; q++)
            if (q != i0 && l[q] > b1) { b1 = l[q]; i1 = q; }

        // renormalized top-2 softmax: w0 = e^{l0} / (e^{l0} + e^{l1})
        const float w0 = 1.0f / (1.0f + expf(b1 - b0));
        const float w1 = 1.0f - w0;

        float* out_idx = out + (size_t)n_tokens * 2;
        out[token * 2 + 0] = w0;
        out[token * 2 + 1] = w1;
        out_idx[token * 2 + 0] = (float)i0;
        out_idx[token * 2 + 1] = (float)i1;
    }
}

extern "C" void kernel_launch(void* const* d_in, const int* in_sizes, int n_in,
                              void* d_out, int out_size)
{
    const float* hid  = (const float*)d_in[0];   // hidden_states
    const float* gate = (const float*)d_in[1];   // gate_weight
    float* out = (float*)d_out;

    const int n_tokens = in_sizes[0] / HDIM;     // 16384
    const int blocks   = (n_tokens + TOK_PER_BLOCK - 1) / TOK_PER_BLOCK;  // 1024

    moe_gate_kernel<<<blocks, 256>>>(
        (const float4*)hid, (const float4*)gate, out, n_tokens);
}